// round 13
// baseline (speedup 1.0000x reference)
#include <cuda_runtime.h>
#include <cuda_bf16.h>
#include <cstdint>

#define NN 50000
#define NE 300000
#define BN_EPS 1e-5f
#define NEG_INF __int_as_float(0xff800000)
#define NBLK 391                       // ceil(NN/128)

// ---------------- scratch (__device__ globals; zero-initialized at load) --------
__device__ float g_xl1[NN * 256];
__device__ float g_xr1[NN * 256];
__device__ float g_x4 [NN * 1024];   // 4 blocks [NN,256]: mu_xl | mu_xr | ls_xl | ls_xr
__device__ float g_agg1[NN * 256];   // conv1 out (+bias), pre-BN
__device__ int   g_cnt [NN];         // re-zeroed by k_scan3 each launch
__device__ int   g_rowptr[NN + 1];
__device__ int   g_cursor[NN];
__device__ int   g_srcs[NE];
__device__ float g_ews [NE];
__device__ int   g_bsum[64];
__device__ int   g_boff[64];
__device__ float g_bn0[12];          // re-zeroed by k_node2h(mu) block 0
__device__ float g_bn1[512];         // accumulated by k_node1; re-zeroed by k_node2h(mu)
// bf16 hi/lo operand planes for the mma.sync GEMM
__device__ unsigned short g_a_hi[NBLK * 128 * 256];   // relu(bn(x1)) hi
__device__ unsigned short g_a_lo[NBLK * 128 * 256];   // residual lo
__device__ unsigned short g_wt_hi[1024 * 256];        // W^T [n][k] hi
__device__ unsigned short g_wt_lo[1024 * 256];

// ---------------- generic helpers ----------------
__device__ __forceinline__ float hsum(float v) {   // 16-lane half-warp butterfly
#pragma unroll
    for (int o = 8; o; o >>= 1) v += __shfl_xor_sync(0xffffffffu, v, o);
    return v;
}
__device__ __forceinline__ uint32_t s2u(const void* p) {
    uint32_t a;
    asm("{ .reg .u64 t; cvta.to.shared.u64 t, %1; cvt.u32.u64 %0, t; }" : "=r"(a) : "l"(p));
    return a;
}
// pack two floats to bf16x2 hi, produce bf16x2 lo residual
__device__ __forceinline__ uint32_t split2(float a, float b, uint32_t& lo) {
    __nv_bfloat16 ha = __float2bfloat16_rn(a), hb = __float2bfloat16_rn(b);
    float ra = a - __bfloat162float(ha), rb = b - __bfloat162float(hb);
    lo = (uint32_t)__bfloat16_as_ushort(__float2bfloat16_rn(ra)) |
         ((uint32_t)__bfloat16_as_ushort(__float2bfloat16_rn(rb)) << 16);
    return (uint32_t)__bfloat16_as_ushort(ha) |
           ((uint32_t)__bfloat16_as_ushort(hb) << 16);
}

// per-edge logit over this lane's 8 channels
__device__ __forceinline__ float edge_logit(
        const float4& xa, const float4& xb, float ew,
        const float4& xrA, const float4& xrB,
        const float4& weA, const float4& weB,
        const float4& atA, const float4& atB) {
    float t = 0.f, v;
    v = xa.x + xrA.x + ew * weA.x; v = v > 0.f ? v : 0.2f * v; t += v * atA.x;
    v = xa.y + xrA.y + ew * weA.y; v = v > 0.f ? v : 0.2f * v; t += v * atA.y;
    v = xa.z + xrA.z + ew * weA.z; v = v > 0.f ? v : 0.2f * v; t += v * atA.z;
    v = xa.w + xrA.w + ew * weA.w; v = v > 0.f ? v : 0.2f * v; t += v * atA.w;
    v = xb.x + xrB.x + ew * weB.x; v = v > 0.f ? v : 0.2f * v; t += v * atB.x;
    v = xb.y + xrB.y + ew * weB.y; v = v > 0.f ? v : 0.2f * v; t += v * atB.y;
    v = xb.z + xrB.z + ew * weB.z; v = v > 0.f ? v : 0.2f * v; t += v * atB.z;
    v = xb.w + xrB.w + ew * weB.w; v = v > 0.f ? v : 0.2f * v; t += v * atB.w;
    return t;
}

#define LDSM4(r, a) \
    asm volatile("ldmatrix.sync.aligned.m8n8.x4.shared.b16 {%0,%1,%2,%3}, [%4];" \
        : "=r"((r)[0]), "=r"((r)[1]), "=r"((r)[2]), "=r"((r)[3]) : "r"(a))
#define MMA(c, a, b) \
    asm volatile("mma.sync.aligned.m16n8k16.row.col.f32.bf16.bf16.f32 " \
        "{%0,%1,%2,%3},{%4,%5,%6,%7},{%8,%9},{%0,%1,%2,%3};" \
        : "+f"((c)[0]), "+f"((c)[1]), "+f"((c)[2]), "+f"((c)[3]) \
        : "r"((a)[0]), "r"((a)[1]), "r"((a)[2]), "r"((a)[3]), "r"((b)[0]), "r"((b)[1]))
#define CP16(saddr, gptr) \
    asm volatile("cp.async.ca.shared.global [%0], [%1], 16;" :: "r"(saddr), "l"(gptr) : "memory")

// ---------------- BN0 statistics ----------------
__global__ void k_bn0_reduce(const float* __restrict__ h) {
    float s[5] = {0, 0, 0, 0, 0}, q[5] = {0, 0, 0, 0, 0};
    int stride = gridDim.x * blockDim.x;
    for (int r = blockIdx.x * blockDim.x + threadIdx.x; r < NN; r += stride) {
#pragma unroll
        for (int c = 0; c < 5; c++) { float v = h[r * 5 + c]; s[c] += v; q[c] += v * v; }
    }
#pragma unroll
    for (int off = 16; off; off >>= 1) {
#pragma unroll
        for (int c = 0; c < 5; c++) {
            s[c] += __shfl_xor_sync(0xffffffffu, s[c], off);
            q[c] += __shfl_xor_sync(0xffffffffu, q[c], off);
        }
    }
    if ((threadIdx.x & 31) == 0) {
#pragma unroll
        for (int c = 0; c < 5; c++) {
            atomicAdd(&g_bn0[c], s[c]);
            atomicAdd(&g_bn0[5 + c], q[c]);
        }
    }
}

// ---------------- W prep: transpose to [n][k] bf16 hi/lo ----------------
__global__ void k_prepw(const float* __restrict__ w0, const float* __restrict__ w1,
                        const float* __restrict__ w2, const float* __restrict__ w3) {
    int idx = blockIdx.x * blockDim.x + threadIdx.x;   // 0..65535
    if (idx >= 1024 * 64) return;
    int q = idx >> 10;          // k quad: k = 4q..4q+3
    int j = idx & 1023;         // global n
    int g = j >> 8, jj = j & 255;
    const float* Wg = (g == 0) ? w0 : (g == 1) ? w1 : (g == 2) ? w2 : w3;
    float v0 = Wg[(4 * q + 0) * 256 + jj];
    float v1 = Wg[(4 * q + 1) * 256 + jj];
    float v2 = Wg[(4 * q + 2) * 256 + jj];
    float v3 = Wg[(4 * q + 3) * 256 + jj];
    uint32_t l0, l1;
    uint32_t h0 = split2(v0, v1, l0);
    uint32_t h1 = split2(v2, v3, l1);
    size_t o = (size_t)j * 256 + 4 * q;
    *(uint2*)&g_wt_hi[o] = make_uint2(h0, h1);
    *(uint2*)&g_wt_lo[o] = make_uint2(l0, l1);
}

// ---------------- BN0 apply + conv1 linears (2-node ILP unroll) ------------------
__global__ void k_lin5(const float* __restrict__ h,
                       const float* __restrict__ bn_g, const float* __restrict__ bn_b,
                       const float* __restrict__ Wl, const float* __restrict__ bl,
                       const float* __restrict__ Wr, const float* __restrict__ br) {
    __shared__ float sWl[5 * 256], sWr[5 * 256];
    __shared__ float sc[5], sh[5];
    int tid = threadIdx.x;
    for (int i = tid; i < 5 * 256; i += blockDim.x) { sWl[i] = Wl[i]; sWr[i] = Wr[i]; }
    if (tid < 5) {
        float mean = g_bn0[tid] * (1.f / NN);
        float var  = g_bn0[5 + tid] * (1.f / NN) - mean * mean;
        float scale = rsqrtf(var + BN_EPS) * bn_g[tid];
        sc[tid] = scale; sh[tid] = bn_b[tid] - mean * scale;
    }
    __syncthreads();
    int j = tid;
    float blj = bl[j], brj = br[j];
    int n0 = blockIdx.x * 32, n1 = min(n0 + 32, NN);
    int n = n0;
    for (; n + 1 < n1; n += 2) {
        float al0 = blj, ar0 = brj, al1 = blj, ar1 = brj;
#pragma unroll
        for (int k = 0; k < 5; k++) {
            float x0 = h[n * 5 + k] * sc[k] + sh[k];
            float x1 = h[(n + 1) * 5 + k] * sc[k] + sh[k];
            float wl_ = sWl[k * 256 + j], wr_ = sWr[k * 256 + j];
            al0 += x0 * wl_; ar0 += x0 * wr_;
            al1 += x1 * wl_; ar1 += x1 * wr_;
        }
        g_xl1[(long long)n * 256 + j] = al0;
        g_xr1[(long long)n * 256 + j] = ar0;
        g_xl1[(long long)(n + 1) * 256 + j] = al1;
        g_xr1[(long long)(n + 1) * 256 + j] = ar1;
    }
    if (n < n1) {
        float al = blj, ar = brj;
#pragma unroll
        for (int k = 0; k < 5; k++) {
            float x = h[n * 5 + k] * sc[k] + sh[k];
            al += x * sWl[k * 256 + j];
            ar += x * sWr[k * 256 + j];
        }
        g_xl1[(long long)n * 256 + j] = al;
        g_xr1[(long long)n * 256 + j] = ar;
    }
}

// ---------------- hist + CSR scan + scatter ----------------
__global__ void k_hist(const int* __restrict__ dst) {
    int e = blockIdx.x * blockDim.x + threadIdx.x;
    if (e < NE) atomicAdd(&g_cnt[dst[e]], 1);
}

__global__ void k_scan1() {
    __shared__ int sm[1024];
    int t = threadIdx.x;
    int n = blockIdx.x * 1024 + t;
    sm[t] = (n < NN) ? g_cnt[n] : 0;
    __syncthreads();
    for (int off = 512; off; off >>= 1) {
        if (t < off) sm[t] += sm[t + off];
        __syncthreads();
    }
    if (t == 0) g_bsum[blockIdx.x] = sm[0];
}

__global__ void k_scan2(int nblocks) {
    __shared__ int sm[64];
    int t = threadIdx.x;
    int v = (t < nblocks) ? g_bsum[t] : 0;
    sm[t] = v;
    __syncthreads();
    for (int off = 1; off < 64; off <<= 1) {
        int u = (t >= off) ? sm[t - off] : 0;
        __syncthreads();
        sm[t] += u;
        __syncthreads();
    }
    g_boff[t] = sm[t] - v;
    if (t == 0) g_rowptr[NN] = NE;
}

__global__ void k_scan3() {
    __shared__ int sm[1024];
    int t = threadIdx.x;
    int n = blockIdx.x * 1024 + t;
    int v = (n < NN) ? g_cnt[n] : 0;
    sm[t] = v;
    __syncthreads();
    for (int off = 1; off < 1024; off <<= 1) {
        int u = (t >= off) ? sm[t - off] : 0;
        __syncthreads();
        sm[t] += u;
        __syncthreads();
    }
    if (n < NN) {
        int excl = g_boff[blockIdx.x] + sm[t] - v;
        g_rowptr[n] = excl;
        g_cursor[n] = excl;
        g_cnt[n] = 0;            // self-zero for next graph replay
    }
}

__global__ void k_scatter(const int* __restrict__ src, const int* __restrict__ dst,
                          const float* __restrict__ ew) {
    int e = blockIdx.x * blockDim.x + threadIdx.x;
    if (e < NE) {
        int p = atomicAdd(&g_cursor[dst[e]], 1);
        g_srcs[p] = src[e];
        g_ews[p]  = ew[e];
    }
}

// ---------------- conv1: warp-per-node ONLINE softmax + fused BN1 stats ----------
__global__ void k_node1(const float* __restrict__ We, const float* __restrict__ att,
                        const float* __restrict__ bias) {
    __shared__ float sst[256], ssq[256];
    int tid = threadIdx.x;
    sst[tid] = 0.f; ssq[tid] = 0.f;
    __syncthreads();

    int n = (blockIdx.x * blockDim.x + tid) >> 5;
    int lane = tid & 31;
    int cb = lane * 8;
    if (n < NN) {
        int js = g_rowptr[n], je = g_rowptr[n + 1];
        const float4* pxr = (const float4*)&g_xr1[(long long)n * 256 + cb];
        float4 xrA = pxr[0], xrB = pxr[1];
        float4 weA = *(const float4*)&We[cb],  weB = *(const float4*)&We[cb + 4];
        float4 atA = *(const float4*)&att[cb], atB = *(const float4*)&att[cb + 4];
        float m = NEG_INF, den = 0.f;
        float acc[8] = {0, 0, 0, 0, 0, 0, 0, 0};
        int j = js;
        for (; j + 1 < je; j += 2) {
            int s0 = g_srcs[j], s1 = g_srcs[j + 1];
            float w0 = g_ews[j], w1 = g_ews[j + 1];
            const float4* p0_ = (const float4*)&g_xl1[(long long)s0 * 256 + cb];
            const float4* p1_ = (const float4*)&g_xl1[(long long)s1 * 256 + cb];
            float4 xa0 = p0_[0], xb0 = p0_[1];
            float4 xa1 = p1_[0], xb1 = p1_[1];
            float t0 = edge_logit(xa0, xb0, w0, xrA, xrB, weA, weB, atA, atB);
            float t1 = edge_logit(xa1, xb1, w1, xrA, xrB, weA, weB, atA, atB);
            float pa = hsum(t0), pb = hsum(t1);
            float nm = fmaxf(m, fmaxf(pa, pb));
            float sc = __expf(m - nm);
            float wa = __expf(pa - nm), wb = __expf(pb - nm);
            m = nm;
            den = den * sc + wa + wb;
            acc[0] = acc[0] * sc + wa * xa0.x + wb * xa1.x;
            acc[1] = acc[1] * sc + wa * xa0.y + wb * xa1.y;
            acc[2] = acc[2] * sc + wa * xa0.z + wb * xa1.z;
            acc[3] = acc[3] * sc + wa * xa0.w + wb * xa1.w;
            acc[4] = acc[4] * sc + wa * xb0.x + wb * xb1.x;
            acc[5] = acc[5] * sc + wa * xb0.y + wb * xb1.y;
            acc[6] = acc[6] * sc + wa * xb0.z + wb * xb1.z;
            acc[7] = acc[7] * sc + wa * xb0.w + wb * xb1.w;
        }
        if (j < je) {
            int s0 = g_srcs[j]; float w0 = g_ews[j];
            const float4* p0_ = (const float4*)&g_xl1[(long long)s0 * 256 + cb];
            float4 xa0 = p0_[0], xb0 = p0_[1];
            float t0 = edge_logit(xa0, xb0, w0, xrA, xrB, weA, weB, atA, atB);
            float pa = hsum(t0);
            float nm = fmaxf(m, pa);
            float sc = __expf(m - nm);
            float wa = __expf(pa - nm);
            m = nm;
            den = den * sc + wa;
            acc[0] = acc[0] * sc + wa * xa0.x; acc[1] = acc[1] * sc + wa * xa0.y;
            acc[2] = acc[2] * sc + wa * xa0.z; acc[3] = acc[3] * sc + wa * xa0.w;
            acc[4] = acc[4] * sc + wa * xb0.x; acc[5] = acc[5] * sc + wa * xb0.y;
            acc[6] = acc[6] * sc + wa * xb0.z; acc[7] = acc[7] * sc + wa * xb0.w;
        }
        float inv = 1.f / (den + 1e-16f);
        float4 bA = *(const float4*)&bias[cb], bB = *(const float4*)&bias[cb + 4];
        float o[8];
        o[0] = acc[0] * inv + bA.x; o[1] = acc[1] * inv + bA.y;
        o[2] = acc[2] * inv + bA.z; o[3] = acc[3] * inv + bA.w;
        o[4] = acc[4] * inv + bB.x; o[5] = acc[5] * inv + bB.y;
        o[6] = acc[6] * inv + bB.z; o[7] = acc[7] * inv + bB.w;
        float4* po = (float4*)&g_agg1[(long long)n * 256 + cb];
        po[0] = make_float4(o[0], o[1], o[2], o[3]);
        po[1] = make_float4(o[4], o[5], o[6], o[7]);
        // fused BN1 stats: accumulate into block-level smem bins
#pragma unroll
        for (int i = 0; i < 8; i++) {
            atomicAdd(&sst[cb + i], o[i]);
            atomicAdd(&ssq[cb + i], o[i] * o[i]);
        }
    }
    __syncthreads();
    atomicAdd(&g_bn1[tid], sst[tid]);
    atomicAdd(&g_bn1[256 + tid], ssq[tid]);
}

// ---------------- A prep: BN (from raw sums) + ReLU, bf16 hi/lo split ------------
__global__ void k_prepa(const float* __restrict__ bg, const float* __restrict__ bb_) {
    int idx = blockIdx.x * blockDim.x + threadIdx.x;   // quad index
    if (idx >= NBLK * 128 * 64) return;
    int r = idx >> 6;
    int q4 = (idx & 63) * 4;
    uint32_t h0 = 0, h1 = 0, l0 = 0, l1 = 0;
    if (r < NN) {
        float4 s4 = *(const float4*)&g_bn1[q4];
        float4 q4v = *(const float4*)&g_bn1[256 + q4];
        float4 gg = *(const float4*)&bg[q4];
        float4 bv = *(const float4*)&bb_[q4];
        float m0 = s4.x * (1.f / NN), m1 = s4.y * (1.f / NN);
        float m2 = s4.z * (1.f / NN), m3 = s4.w * (1.f / NN);
        float A0 = rsqrtf(q4v.x * (1.f / NN) - m0 * m0 + BN_EPS) * gg.x;
        float A1 = rsqrtf(q4v.y * (1.f / NN) - m1 * m1 + BN_EPS) * gg.y;
        float A2 = rsqrtf(q4v.z * (1.f / NN) - m2 * m2 + BN_EPS) * gg.z;
        float A3 = rsqrtf(q4v.w * (1.f / NN) - m3 * m3 + BN_EPS) * gg.w;
        float C0 = bv.x - m0 * A0, C1 = bv.y - m1 * A1;
        float C2 = bv.z - m2 * A2, C3 = bv.w - m3 * A3;
        float4 x = *(const float4*)&g_agg1[(size_t)r * 256 + q4];
        float v0 = fmaxf(x.x * A0 + C0, 0.f);
        float v1 = fmaxf(x.y * A1 + C1, 0.f);
        float v2 = fmaxf(x.z * A2 + C2, 0.f);
        float v3 = fmaxf(x.w * A3 + C3, 0.f);
        h0 = split2(v0, v1, l0);
        h1 = split2(v2, v3, l1);
    }
    size_t o = (size_t)r * 256 + q4;
    *(uint2*)&g_a_hi[o] = make_uint2(h0, h1);
    *(uint2*)&g_a_lo[o] = make_uint2(l0, l1);
}

// ---------------- mma.sync GEMM with 2-stage cp.async pipeline -------------------
#define RS 40
#define PLN (128 * RS * 2)             // 10240 B per plane
__global__ void __launch_bounds__(256) k_gemm_mma(
        const float* __restrict__ b0, const float* __restrict__ b1,
        const float* __restrict__ b2, const float* __restrict__ b3,
        float* __restrict__ Cout) {
    extern __shared__ __align__(16) char dsm[];
    uint32_t sb = s2u(dsm);
    int tid = threadIdx.x;
    int wid = tid >> 5, lane = tid & 31;
    int bx = blockIdx.x;              // 0..7 -> grp*2 + half
    int by = blockIdx.y;
    int grp = bx >> 1, half = bx & 1;
    const float* bb = (grp == 0) ? b0 : (grp == 1) ? b1 : (grp == 2) ? b2 : b3;
    int warp_m = wid & 1;             // 2 x 64 rows
    int warp_n = wid >> 1;            // 4 x 32 cols

    const unsigned short* gAh = g_a_hi + (size_t)by * 128 * 256;
    const unsigned short* gAl = g_a_lo + (size_t)by * 128 * 256;
    const unsigned short* gBh = g_wt_hi + (size_t)bx * 128 * 256;
    const unsigned short* gBl = g_wt_lo + (size_t)bx * 128 * 256;

    int arow = 64 * warp_m + (lane & 15);
    int akb  = (lane >> 4) << 3;
    int brow = 32 * warp_n + (lane & 7) + ((lane >> 4) << 3);
    int bkb  = ((lane >> 3) & 1) << 3;
    int grow0 = tid >> 2, gq0 = (tid & 3) * 8;
    int grow1 = (tid + 256) >> 2, gq1 = ((tid + 256) & 3) * 8;

    float acc[4][4][4];
#pragma unroll
    for (int mi = 0; mi < 4; mi++)
#pragma unroll
        for (int ni = 0; ni < 4; ni++)
#pragma unroll
            for (int r = 0; r < 4; r++) acc[mi][ni][r] = 0.f;

#define ISSUE(stage, cc) do { \
        int k0_ = (cc) * 32; \
        uint32_t base_ = sb + (stage) * 4 * PLN; \
        uint32_t d0_ = base_ + (uint32_t)(grow0 * RS + gq0) * 2; \
        uint32_t d1_ = base_ + (uint32_t)(grow1 * RS + gq1) * 2; \
        size_t s0_ = (size_t)grow0 * 256 + k0_ + gq0; \
        size_t s1_ = (size_t)grow1 * 256 + k0_ + gq1; \
        CP16(d0_,           gAh + s0_); CP16(d1_,           gAh + s1_); \
        CP16(d0_ + PLN,     gAl + s0_); CP16(d1_ + PLN,     gAl + s1_); \
        CP16(d0_ + 2 * PLN, gBh + s0_); CP16(d1_ + 2 * PLN, gBh + s1_); \
        CP16(d0_ + 3 * PLN, gBl + s0_); CP16(d1_ + 3 * PLN, gBl + s1_); \
        asm volatile("cp.async.commit_group;" ::: "memory"); \
    } while (0)

    ISSUE(0, 0);
    for (int c = 0; c < 8; c++) {
        if (c + 1 < 8) {
            ISSUE((c + 1) & 1, c + 1);
            asm volatile("cp.async.wait_group 1;" ::: "memory");
        } else {
            asm volatile("cp.async.wait_group 0;" ::: "memory");
        }
        __syncthreads();
        uint32_t aAh = sb + (c & 1) * 4 * PLN;
        uint32_t aAl = aAh + PLN, aBh = aAh + 2 * PLN, aBl = aAh + 3 * PLN;
#pragma unroll
        for (int ks = 0; ks < 2; ks++) {
            int kk = ks * 16;
            uint32_t ah[4][4], al[4][4];
#pragma unroll
            for (int mi = 0; mi < 4; mi++) {
                uint32_t ad = aAh + (uint32_t)(((arow + 16 * mi) * RS + kk + akb) * 2);
                LDSM4(ah[mi], ad);
            }
            uint32_t bh[4][2];
#pragma unroll
            for (int nb = 0; nb < 2; nb++) {
                uint32_t r4[4];
                uint32_t ad = aBh + (uint32_t)(((brow + 16 * nb) * RS + kk + bkb) * 2);
                LDSM4(r4, ad);
                bh[2 * nb][0] = r4[0]; bh[2 * nb][1] = r4[1];
                bh[2 * nb + 1][0] = r4[2]; bh[2 * nb + 1][1] = r4[3];
            }
#pragma unroll
            for (int mi = 0; mi < 4; mi++)
#pragma unroll
                for (int ni = 0; ni < 4; ni++) MMA(acc[mi][ni], ah[mi], bh[ni]);
            uint32_t bl_[4][2];
#pragma unroll
            for (int nb = 0; nb < 2; nb++) {
                uint32_t r4[4];
                uint32_t ad = aBl + (uint32_t)(((brow + 16 * nb) * RS + kk + bkb) * 2);
                LDSM4(r4, ad);
                bl_[2 * nb][0] = r4[0]; bl_[2 * nb][1] = r4[1];
                bl_[2 * nb + 1][0] = r4[2]; bl_[2 * nb + 1][1] = r4[3];
            }
#pragma unroll
            for (int mi = 0; mi < 4; mi++)
#pragma unroll
                for (int ni = 0; ni < 4; ni++) MMA(acc[mi][ni], ah[mi], bl_[ni]);
#pragma unroll
            for (int mi = 0; mi < 4; mi++) {
                uint32_t ad = aAl + (uint32_t)(((arow + 16 * mi) * RS + kk + akb) * 2);
                LDSM4(al[mi], ad);
            }
#pragma unroll
            for (int mi = 0; mi < 4; mi++)
#pragma unroll
                for (int ni = 0; ni < 4; ni++) MMA(acc[mi][ni], al[mi], bh[ni]);
        }
        __syncthreads();
    }

    float* outp = Cout + (size_t)grp * NN * 256;
    int rbase = by * 128 + 64 * warp_m + (lane >> 2);
    int cfrag = (lane & 3) * 2;
#pragma unroll
    for (int ni = 0; ni < 4; ni++) {
        int col = 32 * warp_n + 8 * ni + cfrag;
        float bx0 = bb[half * 128 + col], bx1 = bb[half * 128 + col + 1];
#pragma unroll
        for (int mi = 0; mi < 4; mi++) {
            int r0 = rbase + 16 * mi;
            if (r0 < NN)
                *(float2*)&outp[(size_t)r0 * 256 + half * 128 + col] =
                    make_float2(acc[mi][ni][0] + bx0, acc[mi][ni][1] + bx1);
            if (r0 + 8 < NN)
                *(float2*)&outp[(size_t)(r0 + 8) * 256 + half * 128 + col] =
                    make_float2(acc[mi][ni][2] + bx0, acc[mi][ni][3] + bx1);
        }
    }
}

// ---------------- mu/ls conv: ONLINE softmax, 2-edge unroll, head-mean -----------
__global__ void k_node2h(const float* __restrict__ xl, const float* __restrict__ xr,
                         const float* __restrict__ We, const float* __restrict__ att,
                         const float* __restrict__ bias, float* __restrict__ out,
                         int zero_bn) {
    // zero BN accumulators for next replay (all consumers already ran)
    if (zero_bn && blockIdx.x == 0) {
        int t = threadIdx.x;
        g_bn1[t] = 0.f; g_bn1[256 + t] = 0.f;
        if (t < 12) g_bn0[t] = 0.f;
    }
    int n = (blockIdx.x * blockDim.x + threadIdx.x) >> 5;
    if (n >= NN) return;
    int lane = threadIdx.x & 31;
    int cb = lane * 8;
    int js = g_rowptr[n], je = g_rowptr[n + 1];
    const float4* pxr = (const float4*)&xr[(long long)n * 256 + cb];
    float4 xrA = pxr[0], xrB = pxr[1];
    float4 weA = *(const float4*)&We[cb],  weB = *(const float4*)&We[cb + 4];
    float4 atA = *(const float4*)&att[cb], atB = *(const float4*)&att[cb + 4];
    float m = NEG_INF, den = 0.f;
    float acc[8] = {0, 0, 0, 0, 0, 0, 0, 0};
    int j = js;
    for (; j + 1 < je; j += 2) {
        int s0 = g_srcs[j], s1 = g_srcs[j + 1];
        float w0 = g_ews[j], w1 = g_ews[j + 1];
        const float4* p0_ = (const float4*)&xl[(long long)s0 * 256 + cb];
        const float4* p1_ = (const float4*)&xl[(long long)s1 * 256 + cb];
        float4 xa0 = p0_[0], xb0 = p0_[1];
        float4 xa1 = p1_[0], xb1 = p1_[1];
        float t0 = edge_logit(xa0, xb0, w0, xrA, xrB, weA, weB, atA, atB);
        float t1 = edge_logit(xa1, xb1, w1, xrA, xrB, weA, weB, atA, atB);
        float pa = hsum(t0), pb = hsum(t1);
        float nm = fmaxf(m, fmaxf(pa, pb));
        float sc = __expf(m - nm);
        float wa = __expf(pa - nm), wb = __expf(pb - nm);
        m = nm;
        den = den * sc + wa + wb;
        acc[0] = acc[0] * sc + wa * xa0.x + wb * xa1.x;
        acc[1] = acc[1] * sc + wa * xa0.y + wb * xa1.y;
        acc[2] = acc[2] * sc + wa * xa0.z + wb * xa1.z;
        acc[3] = acc[3] * sc + wa * xa0.w + wb * xa1.w;
        acc[4] = acc[4] * sc + wa * xb0.x + wb * xb1.x;
        acc[5] = acc[5] * sc + wa * xb0.y + wb * xb1.y;
        acc[6] = acc[6] * sc + wa * xb0.z + wb * xb1.z;
        acc[7] = acc[7] * sc + wa * xb0.w + wb * xb1.w;
    }
    if (j < je) {
        int s0 = g_srcs[j]; float w0 = g_ews[j];
        const float4* p0_ = (const float4*)&xl[(long long)s0 * 256 + cb];
        float4 xa0 = p0_[0], xb0 = p0_[1];
        float t0 = edge_logit(xa0, xb0, w0, xrA, xrB, weA, weB, atA, atB);
        float pa = hsum(t0);
        float nm = fmaxf(m, pa);
        float sc = __expf(m - nm);
        float wa = __expf(pa - nm);
        m = nm;
        den = den * sc + wa;
        acc[0] = acc[0] * sc + wa * xa0.x; acc[1] = acc[1] * sc + wa * xa0.y;
        acc[2] = acc[2] * sc + wa * xa0.z; acc[3] = acc[3] * sc + wa * xa0.w;
        acc[4] = acc[4] * sc + wa * xb0.x; acc[5] = acc[5] * sc + wa * xb0.y;
        acc[6] = acc[6] * sc + wa * xb0.z; acc[7] = acc[7] * sc + wa * xb0.w;
    }
    float inv = 1.f / (den + 1e-16f);
    float r8[8];
#pragma unroll
    for (int k = 0; k < 8; k++) {
        float mine = acc[k] * inv;
        float peer = __shfl_xor_sync(0xffffffffu, mine, 16);
        r8[k] = 0.5f * (mine + peer);
    }
    if (lane < 16) {
        float4 bA = *(const float4*)&bias[cb], bB = *(const float4*)&bias[cb + 4];
        float4* po = (float4*)&out[(long long)n * 128 + cb];
        po[0] = make_float4(r8[0] + bA.x, r8[1] + bA.y, r8[2] + bA.z, r8[3] + bA.w);
        po[1] = make_float4(r8[4] + bB.x, r8[5] + bB.y, r8[6] + bB.z, r8[7] + bB.w);
    }
}

// ---------------- launch ----------------
extern "C" void kernel_launch(void* const* d_in, const int* in_sizes, int n_in,
                              void* d_out, int out_size) {
    const float* h       = (const float*)d_in[0];
    const int*   ei      = (const int*)d_in[1];
    const float* ew      = (const float*)d_in[2];
    const float* bn0_g   = (const float*)d_in[3];
    const float* bn0_b   = (const float*)d_in[4];
    const float* bn1_g   = (const float*)d_in[5];
    const float* bn1_b   = (const float*)d_in[6];
    const float* c1_Wl   = (const float*)d_in[7];
    const float* c1_bl   = (const float*)d_in[8];
    const float* c1_Wr   = (const float*)d_in[9];
    const float* c1_br   = (const float*)d_in[10];
    const float* c1_We   = (const float*)d_in[11];
    const float* c1_att  = (const float*)d_in[12];
    const float* c1_bias = (const float*)d_in[13];
    const float* mu_Wl   = (const float*)d_in[14];
    const float* mu_bl   = (const float*)d_in[15];
    const float* mu_Wr   = (const float*)d_in[16];
    const float* mu_br   = (const float*)d_in[17];
    const float* mu_We   = (const float*)d_in[18];
    const float* mu_att  = (const float*)d_in[19];
    const float* mu_bias = (const float*)d_in[20];
    const float* ls_Wl   = (const float*)d_in[21];
    const float* ls_bl   = (const float*)d_in[22];
    const float* ls_Wr   = (const float*)d_in[23];
    const float* ls_br   = (const float*)d_in[24];
    const float* ls_We   = (const float*)d_in[25];
    const float* ls_att  = (const float*)d_in[26];
    const float* ls_bias = (const float*)d_in[27];
    float* out = (float*)d_out;

    const int* src = ei;
    const int* dst = ei + NE;

    float* x4;
    cudaGetSymbolAddress((void**)&x4, g_x4);

    const int TB = 256;
    int eb = (NE + TB - 1) / TB;
    int nodeWarpBlocks = (NN * 32 + TB - 1) / TB;
    int scanBlocks = (NN + 1023) / 1024;   // 49
    const int GEMM_SMEM = 8 * PLN;         // 81920 B

    cudaFuncSetAttribute(k_gemm_mma, cudaFuncAttributeMaxDynamicSharedMemorySize, GEMM_SMEM);

    // fork: side stream runs the CSR chain concurrently with prepw+bn0+lin5
    cudaStream_t s2;
    cudaStreamCreateWithFlags(&s2, cudaStreamNonBlocking);
    cudaEvent_t ef, ej;
    cudaEventCreateWithFlags(&ef, cudaEventDisableTiming);
    cudaEventCreateWithFlags(&ej, cudaEventDisableTiming);

    cudaEventRecord(ef, 0);
    cudaStreamWaitEvent(s2, ef, 0);

    // side stream: CSR build
    k_hist<<<eb, TB, 0, s2>>>(dst);
    k_scan1<<<scanBlocks, 1024, 0, s2>>>();
    k_scan2<<<1, 64, 0, s2>>>(scanBlocks);
    k_scan3<<<scanBlocks, 1024, 0, s2>>>();
    k_scatter<<<eb, TB, 0, s2>>>(src, dst, ew);
    cudaEventRecord(ej, s2);

    // main stream: weight prep + BN0 + conv1 linears
    k_prepw<<<(1024 * 64 + TB - 1) / TB, TB>>>(mu_Wl, mu_Wr, ls_Wl, ls_Wr);
    k_bn0_reduce<<<64, TB>>>(h);
    k_lin5<<<(NN + 31) / 32, TB>>>(h, bn0_g, bn0_b, c1_Wl, c1_bl, c1_Wr, c1_br);

    // join
    cudaStreamWaitEvent(0, ej, 0);

    k_node1<<<nodeWarpBlocks, TB>>>(c1_We, c1_att, c1_bias);   // includes BN1 stats

    k_prepa<<<(NBLK * 128 * 64 + TB - 1) / TB, TB>>>(bn1_g, bn1_b);

    dim3 gg(8, NBLK);
    k_gemm_mma<<<gg, 256, GEMM_SMEM>>>(mu_bl, mu_br, ls_bl, ls_br, x4);

    // SEQUENTIAL mu then ls convs (concurrent version thrashed L2 — R12 regression)
    k_node2h<<<nodeWarpBlocks, TB>>>(x4, x4 + (long long)NN * 256,
                                     mu_We, mu_att, mu_bias, out, 1);
    k_node2h<<<nodeWarpBlocks, TB>>>(x4 + 2ll * NN * 256, x4 + 3ll * NN * 256,
                                     ls_We, ls_att, ls_bias,
                                     out + (long long)NN * 128, 0);
}

// round 14
// speedup vs baseline: 1.0498x; 1.0498x over previous
#include <cuda_runtime.h>
#include <cuda_bf16.h>
#include <cstdint>

#define NN 50000
#define NE 300000
#define BN_EPS 1e-5f
#define NEG_INF __int_as_float(0xff800000)
#define NBLK 391                       // ceil(NN/128)

// ---------------- scratch (__device__ globals; zero-initialized at load) --------
__device__ float g_xl1[NN * 256];
__device__ float g_xr1[NN * 256];
__device__ float g_x4 [NN * 1024];   // 4 blocks [NN,256]: mu_xl | mu_xr | ls_xl | ls_xr
__device__ float g_agg1[NN * 256];   // conv1 out (+bias), pre-BN
__device__ int   g_cnt [NN];         // re-zeroed by k_scan3 each launch
__device__ int   g_rowptr[NN + 1];
__device__ int   g_cursor[NN];
__device__ int   g_srcs[NE];
__device__ float g_ews [NE];
__device__ int   g_bsum[64];
__device__ int   g_boff[64];
__device__ float g_bn0[12];          // re-zeroed by k_node1 block 0
__device__ float g_bn1[512];         // re-zeroed by k_node1 block 0
// bf16 hi/lo operand planes for the mma.sync GEMM
__device__ unsigned short g_a_hi[NBLK * 128 * 256];   // relu(bn(x1)) hi
__device__ unsigned short g_a_lo[NBLK * 128 * 256];   // residual lo
__device__ unsigned short g_wt_hi[1024 * 256];        // W^T [n][k] hi
__device__ unsigned short g_wt_lo[1024 * 256];

// ---------------- generic helpers ----------------
__device__ __forceinline__ float hsum(float v) {   // 16-lane half-warp butterfly
#pragma unroll
    for (int o = 8; o; o >>= 1) v += __shfl_xor_sync(0xffffffffu, v, o);
    return v;
}
__device__ __forceinline__ uint32_t s2u(const void* p) {
    uint32_t a;
    asm("{ .reg .u64 t; cvta.to.shared.u64 t, %1; cvt.u32.u64 %0, t; }" : "=r"(a) : "l"(p));
    return a;
}
// pack two floats to bf16x2 hi, produce bf16x2 lo residual
__device__ __forceinline__ uint32_t split2(float a, float b, uint32_t& lo) {
    __nv_bfloat16 ha = __float2bfloat16_rn(a), hb = __float2bfloat16_rn(b);
    float ra = a - __bfloat162float(ha), rb = b - __bfloat162float(hb);
    lo = (uint32_t)__bfloat16_as_ushort(__float2bfloat16_rn(ra)) |
         ((uint32_t)__bfloat16_as_ushort(__float2bfloat16_rn(rb)) << 16);
    return (uint32_t)__bfloat16_as_ushort(ha) |
           ((uint32_t)__bfloat16_as_ushort(hb) << 16);
}

// per-edge logit over this lane's 8 channels (inline fn: macro-hygiene-safe)
__device__ __forceinline__ float edge_logit(
        const float4& xa, const float4& xb, float ew,
        const float4& xrA, const float4& xrB,
        const float4& weA, const float4& weB,
        const float4& atA, const float4& atB) {
    float t = 0.f, v;
    v = xa.x + xrA.x + ew * weA.x; v = v > 0.f ? v : 0.2f * v; t += v * atA.x;
    v = xa.y + xrA.y + ew * weA.y; v = v > 0.f ? v : 0.2f * v; t += v * atA.y;
    v = xa.z + xrA.z + ew * weA.z; v = v > 0.f ? v : 0.2f * v; t += v * atA.z;
    v = xa.w + xrA.w + ew * weA.w; v = v > 0.f ? v : 0.2f * v; t += v * atA.w;
    v = xb.x + xrB.x + ew * weB.x; v = v > 0.f ? v : 0.2f * v; t += v * atB.x;
    v = xb.y + xrB.y + ew * weB.y; v = v > 0.f ? v : 0.2f * v; t += v * atB.y;
    v = xb.z + xrB.z + ew * weB.z; v = v > 0.f ? v : 0.2f * v; t += v * atB.z;
    v = xb.w + xrB.w + ew * weB.w; v = v > 0.f ? v : 0.2f * v; t += v * atB.w;
    return t;
}

#define LDSM4(r, a) \
    asm volatile("ldmatrix.sync.aligned.m8n8.x4.shared.b16 {%0,%1,%2,%3}, [%4];" \
        : "=r"((r)[0]), "=r"((r)[1]), "=r"((r)[2]), "=r"((r)[3]) : "r"(a))
#define MMA(c, a, b) \
    asm volatile("mma.sync.aligned.m16n8k16.row.col.f32.bf16.bf16.f32 " \
        "{%0,%1,%2,%3},{%4,%5,%6,%7},{%8,%9},{%0,%1,%2,%3};" \
        : "+f"((c)[0]), "+f"((c)[1]), "+f"((c)[2]), "+f"((c)[3]) \
        : "r"((a)[0]), "r"((a)[1]), "r"((a)[2]), "r"((a)[3]), "r"((b)[0]), "r"((b)[1]))
#define CP16(saddr, gptr) \
    asm volatile("cp.async.ca.shared.global [%0], [%1], 16;" :: "r"(saddr), "l"(gptr) : "memory")

// ---------------- BN0 statistics ----------------
__global__ void k_bn0_reduce(const float* __restrict__ h) {
    float s[5] = {0, 0, 0, 0, 0}, q[5] = {0, 0, 0, 0, 0};
    int stride = gridDim.x * blockDim.x;
    for (int r = blockIdx.x * blockDim.x + threadIdx.x; r < NN; r += stride) {
#pragma unroll
        for (int c = 0; c < 5; c++) { float v = h[r * 5 + c]; s[c] += v; q[c] += v * v; }
    }
#pragma unroll
    for (int off = 16; off; off >>= 1) {
#pragma unroll
        for (int c = 0; c < 5; c++) {
            s[c] += __shfl_xor_sync(0xffffffffu, s[c], off);
            q[c] += __shfl_xor_sync(0xffffffffu, q[c], off);
        }
    }
    if ((threadIdx.x & 31) == 0) {
#pragma unroll
        for (int c = 0; c < 5; c++) {
            atomicAdd(&g_bn0[c], s[c]);
            atomicAdd(&g_bn0[5 + c], q[c]);
        }
    }
}

// ---------------- W prep: transpose to [n][k] bf16 hi/lo ----------------
__global__ void k_prepw(const float* __restrict__ w0, const float* __restrict__ w1,
                        const float* __restrict__ w2, const float* __restrict__ w3) {
    int idx = blockIdx.x * blockDim.x + threadIdx.x;   // 0..65535
    if (idx >= 1024 * 64) return;
    int q = idx >> 10;          // k quad: k = 4q..4q+3
    int j = idx & 1023;         // global n
    int g = j >> 8, jj = j & 255;
    const float* Wg = (g == 0) ? w0 : (g == 1) ? w1 : (g == 2) ? w2 : w3;
    float v0 = Wg[(4 * q + 0) * 256 + jj];
    float v1 = Wg[(4 * q + 1) * 256 + jj];
    float v2 = Wg[(4 * q + 2) * 256 + jj];
    float v3 = Wg[(4 * q + 3) * 256 + jj];
    uint32_t l0, l1;
    uint32_t h0 = split2(v0, v1, l0);
    uint32_t h1 = split2(v2, v3, l1);
    size_t o = (size_t)j * 256 + 4 * q;
    *(uint2*)&g_wt_hi[o] = make_uint2(h0, h1);
    *(uint2*)&g_wt_lo[o] = make_uint2(l0, l1);
}

// ---------------- BN0 apply + conv1 linears (2-node ILP unroll) ------------------
__global__ void k_lin5(const float* __restrict__ h,
                       const float* __restrict__ bn_g, const float* __restrict__ bn_b,
                       const float* __restrict__ Wl, const float* __restrict__ bl,
                       const float* __restrict__ Wr, const float* __restrict__ br) {
    __shared__ float sWl[5 * 256], sWr[5 * 256];
    __shared__ float sc[5], sh[5];
    int tid = threadIdx.x;
    for (int i = tid; i < 5 * 256; i += blockDim.x) { sWl[i] = Wl[i]; sWr[i] = Wr[i]; }
    if (tid < 5) {
        float mean = g_bn0[tid] * (1.f / NN);
        float var  = g_bn0[5 + tid] * (1.f / NN) - mean * mean;
        float scale = rsqrtf(var + BN_EPS) * bn_g[tid];
        sc[tid] = scale; sh[tid] = bn_b[tid] - mean * scale;
    }
    __syncthreads();
    int j = tid;
    float blj = bl[j], brj = br[j];
    int n0 = blockIdx.x * 32, n1 = min(n0 + 32, NN);
    int n = n0;
    for (; n + 1 < n1; n += 2) {
        float al0 = blj, ar0 = brj, al1 = blj, ar1 = brj;
#pragma unroll
        for (int k = 0; k < 5; k++) {
            float x0 = h[n * 5 + k] * sc[k] + sh[k];
            float x1 = h[(n + 1) * 5 + k] * sc[k] + sh[k];
            float wl_ = sWl[k * 256 + j], wr_ = sWr[k * 256 + j];
            al0 += x0 * wl_; ar0 += x0 * wr_;
            al1 += x1 * wl_; ar1 += x1 * wr_;
        }
        g_xl1[(long long)n * 256 + j] = al0;
        g_xr1[(long long)n * 256 + j] = ar0;
        g_xl1[(long long)(n + 1) * 256 + j] = al1;
        g_xr1[(long long)(n + 1) * 256 + j] = ar1;
    }
    if (n < n1) {
        float al = blj, ar = brj;
#pragma unroll
        for (int k = 0; k < 5; k++) {
            float x = h[n * 5 + k] * sc[k] + sh[k];
            al += x * sWl[k * 256 + j];
            ar += x * sWr[k * 256 + j];
        }
        g_xl1[(long long)n * 256 + j] = al;
        g_xr1[(long long)n * 256 + j] = ar;
    }
}

// ---------------- hist + CSR scan + scatter ----------------
__global__ void k_hist(const int* __restrict__ dst) {
    int e = blockIdx.x * blockDim.x + threadIdx.x;
    if (e < NE) atomicAdd(&g_cnt[dst[e]], 1);
}

__global__ void k_scan1() {
    __shared__ int sm[1024];
    int t = threadIdx.x;
    int n = blockIdx.x * 1024 + t;
    sm[t] = (n < NN) ? g_cnt[n] : 0;
    __syncthreads();
    for (int off = 512; off; off >>= 1) {
        if (t < off) sm[t] += sm[t + off];
        __syncthreads();
    }
    if (t == 0) g_bsum[blockIdx.x] = sm[0];
}

__global__ void k_scan2(int nblocks) {
    __shared__ int sm[64];
    int t = threadIdx.x;
    int v = (t < nblocks) ? g_bsum[t] : 0;
    sm[t] = v;
    __syncthreads();
    for (int off = 1; off < 64; off <<= 1) {
        int u = (t >= off) ? sm[t - off] : 0;
        __syncthreads();
        sm[t] += u;
        __syncthreads();
    }
    g_boff[t] = sm[t] - v;
    if (t == 0) g_rowptr[NN] = NE;
}

__global__ void k_scan3() {
    __shared__ int sm[1024];
    int t = threadIdx.x;
    int n = blockIdx.x * 1024 + t;
    int v = (n < NN) ? g_cnt[n] : 0;
    sm[t] = v;
    __syncthreads();
    for (int off = 1; off < 1024; off <<= 1) {
        int u = (t >= off) ? sm[t - off] : 0;
        __syncthreads();
        sm[t] += u;
        __syncthreads();
    }
    if (n < NN) {
        int excl = g_boff[blockIdx.x] + sm[t] - v;
        g_rowptr[n] = excl;
        g_cursor[n] = excl;
        g_cnt[n] = 0;            // self-zero for next graph replay
    }
}

__global__ void k_scatter(const int* __restrict__ src, const int* __restrict__ dst,
                          const float* __restrict__ ew) {
    int e = blockIdx.x * blockDim.x + threadIdx.x;
    if (e < NE) {
        int p = atomicAdd(&g_cursor[dst[e]], 1);
        g_srcs[p] = src[e];
        g_ews[p]  = ew[e];
    }
}

// ---------------- conv1: warp-per-node ONLINE softmax, 2-edge unroll -------------
__global__ void k_node1(const float* __restrict__ We, const float* __restrict__ att,
                        const float* __restrict__ bias) {
    // self-zero BN accumulators for next replay (consumers already ran this launch)
    if (blockIdx.x == 0) {
        int t = threadIdx.x;
        g_bn1[t] = 0.f; g_bn1[256 + t] = 0.f;
        if (t < 12) g_bn0[t] = 0.f;
    }
    int n = (blockIdx.x * blockDim.x + threadIdx.x) >> 5;
    if (n >= NN) return;
    int lane = threadIdx.x & 31;
    int cb = lane * 8;
    int js = g_rowptr[n], je = g_rowptr[n + 1];
    const float4* pxr = (const float4*)&g_xr1[(long long)n * 256 + cb];
    float4 xrA = pxr[0], xrB = pxr[1];
    float4 weA = *(const float4*)&We[cb],  weB = *(const float4*)&We[cb + 4];
    float4 atA = *(const float4*)&att[cb], atB = *(const float4*)&att[cb + 4];
    float m = NEG_INF, den = 0.f;
    float acc[8] = {0, 0, 0, 0, 0, 0, 0, 0};
    int j = js;
    for (; j + 1 < je; j += 2) {
        int s0 = g_srcs[j], s1 = g_srcs[j + 1];
        float w0 = g_ews[j], w1 = g_ews[j + 1];
        const float4* p0_ = (const float4*)&g_xl1[(long long)s0 * 256 + cb];
        const float4* p1_ = (const float4*)&g_xl1[(long long)s1 * 256 + cb];
        float4 xa0 = p0_[0], xb0 = p0_[1];
        float4 xa1 = p1_[0], xb1 = p1_[1];
        float t0 = edge_logit(xa0, xb0, w0, xrA, xrB, weA, weB, atA, atB);
        float t1 = edge_logit(xa1, xb1, w1, xrA, xrB, weA, weB, atA, atB);
        float pa = hsum(t0), pb = hsum(t1);
        float nm = fmaxf(m, fmaxf(pa, pb));
        float sc = __expf(m - nm);
        float wa = __expf(pa - nm), wb = __expf(pb - nm);
        m = nm;
        den = den * sc + wa + wb;
        acc[0] = acc[0] * sc + wa * xa0.x + wb * xa1.x;
        acc[1] = acc[1] * sc + wa * xa0.y + wb * xa1.y;
        acc[2] = acc[2] * sc + wa * xa0.z + wb * xa1.z;
        acc[3] = acc[3] * sc + wa * xa0.w + wb * xa1.w;
        acc[4] = acc[4] * sc + wa * xb0.x + wb * xb1.x;
        acc[5] = acc[5] * sc + wa * xb0.y + wb * xb1.y;
        acc[6] = acc[6] * sc + wa * xb0.z + wb * xb1.z;
        acc[7] = acc[7] * sc + wa * xb0.w + wb * xb1.w;
    }
    if (j < je) {
        int s0 = g_srcs[j]; float w0 = g_ews[j];
        const float4* p0_ = (const float4*)&g_xl1[(long long)s0 * 256 + cb];
        float4 xa0 = p0_[0], xb0 = p0_[1];
        float t0 = edge_logit(xa0, xb0, w0, xrA, xrB, weA, weB, atA, atB);
        float pa = hsum(t0);
        float nm = fmaxf(m, pa);
        float sc = __expf(m - nm);
        float wa = __expf(pa - nm);
        m = nm;
        den = den * sc + wa;
        acc[0] = acc[0] * sc + wa * xa0.x; acc[1] = acc[1] * sc + wa * xa0.y;
        acc[2] = acc[2] * sc + wa * xa0.z; acc[3] = acc[3] * sc + wa * xa0.w;
        acc[4] = acc[4] * sc + wa * xb0.x; acc[5] = acc[5] * sc + wa * xb0.y;
        acc[6] = acc[6] * sc + wa * xb0.z; acc[7] = acc[7] * sc + wa * xb0.w;
    }
    float inv = 1.f / (den + 1e-16f);
    float4 bA = *(const float4*)&bias[cb], bB = *(const float4*)&bias[cb + 4];
    float4* po = (float4*)&g_agg1[(long long)n * 256 + cb];
    po[0] = make_float4(acc[0] * inv + bA.x, acc[1] * inv + bA.y,
                        acc[2] * inv + bA.z, acc[3] * inv + bA.w);
    po[1] = make_float4(acc[4] * inv + bB.x, acc[5] * inv + bB.y,
                        acc[6] * inv + bB.z, acc[7] * inv + bB.w);
}

// ---------------- BN1 statistics ----------------
__global__ void k_bn1_reduce() {
    int c = threadIdx.x;
    float s = 0.f, q = 0.f;
    for (int r = blockIdx.x; r < NN; r += gridDim.x) {
        float v = g_agg1[(long long)r * 256 + c];
        s += v; q += v * v;
    }
    atomicAdd(&g_bn1[c], s);
    atomicAdd(&g_bn1[256 + c], q);
}

// ---------------- A prep: BN (from raw sums) + ReLU, bf16 hi/lo split ------------
__global__ void k_prepa(const float* __restrict__ bg, const float* __restrict__ bb_) {
    int idx = blockIdx.x * blockDim.x + threadIdx.x;   // quad index
    if (idx >= NBLK * 128 * 64) return;
    int r = idx >> 6;
    int q4 = (idx & 63) * 4;
    uint32_t h0 = 0, h1 = 0, l0 = 0, l1 = 0;
    if (r < NN) {
        float4 s4 = *(const float4*)&g_bn1[q4];
        float4 q4v = *(const float4*)&g_bn1[256 + q4];
        float4 gg = *(const float4*)&bg[q4];
        float4 bv = *(const float4*)&bb_[q4];
        float m0 = s4.x * (1.f / NN), m1 = s4.y * (1.f / NN);
        float m2 = s4.z * (1.f / NN), m3 = s4.w * (1.f / NN);
        float A0 = rsqrtf(q4v.x * (1.f / NN) - m0 * m0 + BN_EPS) * gg.x;
        float A1 = rsqrtf(q4v.y * (1.f / NN) - m1 * m1 + BN_EPS) * gg.y;
        float A2 = rsqrtf(q4v.z * (1.f / NN) - m2 * m2 + BN_EPS) * gg.z;
        float A3 = rsqrtf(q4v.w * (1.f / NN) - m3 * m3 + BN_EPS) * gg.w;
        float C0 = bv.x - m0 * A0, C1 = bv.y - m1 * A1;
        float C2 = bv.z - m2 * A2, C3 = bv.w - m3 * A3;
        float4 x = *(const float4*)&g_agg1[(size_t)r * 256 + q4];
        float v0 = fmaxf(x.x * A0 + C0, 0.f);
        float v1 = fmaxf(x.y * A1 + C1, 0.f);
        float v2 = fmaxf(x.z * A2 + C2, 0.f);
        float v3 = fmaxf(x.w * A3 + C3, 0.f);
        h0 = split2(v0, v1, l0);
        h1 = split2(v2, v3, l1);
    }
    size_t o = (size_t)r * 256 + q4;
    *(uint2*)&g_a_hi[o] = make_uint2(h0, h1);
    *(uint2*)&g_a_lo[o] = make_uint2(l0, l1);
}

// ---------------- mma.sync GEMM with 2-stage cp.async pipeline -------------------
#define RS 40
#define PLN (128 * RS * 2)             // 10240 B per plane
__global__ void __launch_bounds__(256) k_gemm_mma(
        const float* __restrict__ b0, const float* __restrict__ b1,
        const float* __restrict__ b2, const float* __restrict__ b3,
        float* __restrict__ Cout) {
    extern __shared__ __align__(16) char dsm[];
    uint32_t sb = s2u(dsm);
    int tid = threadIdx.x;
    int wid = tid >> 5, lane = tid & 31;
    int bx = blockIdx.x;              // 0..7 -> grp*2 + half
    int by = blockIdx.y;
    int grp = bx >> 1, half = bx & 1;
    const float* bb = (grp == 0) ? b0 : (grp == 1) ? b1 : (grp == 2) ? b2 : b3;
    int warp_m = wid & 1;             // 2 x 64 rows
    int warp_n = wid >> 1;            // 4 x 32 cols

    const unsigned short* gAh = g_a_hi + (size_t)by * 128 * 256;
    const unsigned short* gAl = g_a_lo + (size_t)by * 128 * 256;
    const unsigned short* gBh = g_wt_hi + (size_t)bx * 128 * 256;
    const unsigned short* gBl = g_wt_lo + (size_t)bx * 128 * 256;

    int arow = 64 * warp_m + (lane & 15);
    int akb  = (lane >> 4) << 3;
    int brow = 32 * warp_n + (lane & 7) + ((lane >> 4) << 3);
    int bkb  = ((lane >> 3) & 1) << 3;
    int grow0 = tid >> 2, gq0 = (tid & 3) * 8;
    int grow1 = (tid + 256) >> 2, gq1 = ((tid + 256) & 3) * 8;

    float acc[4][4][4];
#pragma unroll
    for (int mi = 0; mi < 4; mi++)
#pragma unroll
        for (int ni = 0; ni < 4; ni++)
#pragma unroll
            for (int r = 0; r < 4; r++) acc[mi][ni][r] = 0.f;

#define ISSUE(stage, cc) do { \
        int k0_ = (cc) * 32; \
        uint32_t base_ = sb + (stage) * 4 * PLN; \
        uint32_t d0_ = base_ + (uint32_t)(grow0 * RS + gq0) * 2; \
        uint32_t d1_ = base_ + (uint32_t)(grow1 * RS + gq1) * 2; \
        size_t s0_ = (size_t)grow0 * 256 + k0_ + gq0; \
        size_t s1_ = (size_t)grow1 * 256 + k0_ + gq1; \
        CP16(d0_,           gAh + s0_); CP16(d1_,           gAh + s1_); \
        CP16(d0_ + PLN,     gAl + s0_); CP16(d1_ + PLN,     gAl + s1_); \
        CP16(d0_ + 2 * PLN, gBh + s0_); CP16(d1_ + 2 * PLN, gBh + s1_); \
        CP16(d0_ + 3 * PLN, gBl + s0_); CP16(d1_ + 3 * PLN, gBl + s1_); \
        asm volatile("cp.async.commit_group;" ::: "memory"); \
    } while (0)

    ISSUE(0, 0);
    for (int c = 0; c < 8; c++) {
        if (c + 1 < 8) {
            ISSUE((c + 1) & 1, c + 1);
            asm volatile("cp.async.wait_group 1;" ::: "memory");
        } else {
            asm volatile("cp.async.wait_group 0;" ::: "memory");
        }
        __syncthreads();
        uint32_t aAh = sb + (c & 1) * 4 * PLN;
        uint32_t aAl = aAh + PLN, aBh = aAh + 2 * PLN, aBl = aAh + 3 * PLN;
#pragma unroll
        for (int ks = 0; ks < 2; ks++) {
            int kk = ks * 16;
            uint32_t ah[4][4], al[4][4];
#pragma unroll
            for (int mi = 0; mi < 4; mi++) {
                uint32_t ad = aAh + (uint32_t)(((arow + 16 * mi) * RS + kk + akb) * 2);
                LDSM4(ah[mi], ad);
            }
            uint32_t bh[4][2];
#pragma unroll
            for (int nb = 0; nb < 2; nb++) {
                uint32_t r4[4];
                uint32_t ad = aBh + (uint32_t)(((brow + 16 * nb) * RS + kk + bkb) * 2);
                LDSM4(r4, ad);
                bh[2 * nb][0] = r4[0]; bh[2 * nb][1] = r4[1];
                bh[2 * nb + 1][0] = r4[2]; bh[2 * nb + 1][1] = r4[3];
            }
#pragma unroll
            for (int mi = 0; mi < 4; mi++)
#pragma unroll
                for (int ni = 0; ni < 4; ni++) MMA(acc[mi][ni], ah[mi], bh[ni]);
            uint32_t bl_[4][2];
#pragma unroll
            for (int nb = 0; nb < 2; nb++) {
                uint32_t r4[4];
                uint32_t ad = aBl + (uint32_t)(((brow + 16 * nb) * RS + kk + bkb) * 2);
                LDSM4(r4, ad);
                bl_[2 * nb][0] = r4[0]; bl_[2 * nb][1] = r4[1];
                bl_[2 * nb + 1][0] = r4[2]; bl_[2 * nb + 1][1] = r4[3];
            }
#pragma unroll
            for (int mi = 0; mi < 4; mi++)
#pragma unroll
                for (int ni = 0; ni < 4; ni++) MMA(acc[mi][ni], ah[mi], bl_[ni]);
#pragma unroll
            for (int mi = 0; mi < 4; mi++) {
                uint32_t ad = aAl + (uint32_t)(((arow + 16 * mi) * RS + kk + akb) * 2);
                LDSM4(al[mi], ad);
            }
#pragma unroll
            for (int mi = 0; mi < 4; mi++)
#pragma unroll
                for (int ni = 0; ni < 4; ni++) MMA(acc[mi][ni], al[mi], bh[ni]);
        }
        __syncthreads();
    }

    float* outp = Cout + (size_t)grp * NN * 256;
    int rbase = by * 128 + 64 * warp_m + (lane >> 2);
    int cfrag = (lane & 3) * 2;
#pragma unroll
    for (int ni = 0; ni < 4; ni++) {
        int col = 32 * warp_n + 8 * ni + cfrag;
        float bx0 = bb[half * 128 + col], bx1 = bb[half * 128 + col + 1];
#pragma unroll
        for (int mi = 0; mi < 4; mi++) {
            int r0 = rbase + 16 * mi;
            if (r0 < NN)
                *(float2*)&outp[(size_t)r0 * 256 + half * 128 + col] =
                    make_float2(acc[mi][ni][0] + bx0, acc[mi][ni][1] + bx1);
            if (r0 + 8 < NN)
                *(float2*)&outp[(size_t)(r0 + 8) * 256 + half * 128 + col] =
                    make_float2(acc[mi][ni][2] + bx0, acc[mi][ni][3] + bx1);
        }
    }
}

// ---------------- mu/ls conv: ONLINE softmax, 2-edge unroll, head-mean -----------
__global__ void k_node2h(const float* __restrict__ xl, const float* __restrict__ xr,
                         const float* __restrict__ We, const float* __restrict__ att,
                         const float* __restrict__ bias, float* __restrict__ out) {
    int n = (blockIdx.x * blockDim.x + threadIdx.x) >> 5;
    if (n >= NN) return;
    int lane = threadIdx.x & 31;
    int cb = lane * 8;
    int js = g_rowptr[n], je = g_rowptr[n + 1];
    const float4* pxr = (const float4*)&xr[(long long)n * 256 + cb];
    float4 xrA = pxr[0], xrB = pxr[1];
    float4 weA = *(const float4*)&We[cb],  weB = *(const float4*)&We[cb + 4];
    float4 atA = *(const float4*)&att[cb], atB = *(const float4*)&att[cb + 4];
    float m = NEG_INF, den = 0.f;
    float acc[8] = {0, 0, 0, 0, 0, 0, 0, 0};
    int j = js;
    for (; j + 1 < je; j += 2) {
        int s0 = g_srcs[j], s1 = g_srcs[j + 1];
        float w0 = g_ews[j], w1 = g_ews[j + 1];
        const float4* p0_ = (const float4*)&xl[(long long)s0 * 256 + cb];
        const float4* p1_ = (const float4*)&xl[(long long)s1 * 256 + cb];
        float4 xa0 = p0_[0], xb0 = p0_[1];
        float4 xa1 = p1_[0], xb1 = p1_[1];
        float t0 = edge_logit(xa0, xb0, w0, xrA, xrB, weA, weB, atA, atB);
        float t1 = edge_logit(xa1, xb1, w1, xrA, xrB, weA, weB, atA, atB);
        float pa = hsum(t0), pb = hsum(t1);
        float nm = fmaxf(m, fmaxf(pa, pb));
        float sc = __expf(m - nm);
        float wa = __expf(pa - nm), wb = __expf(pb - nm);
        m = nm;
        den = den * sc + wa + wb;
        acc[0] = acc[0] * sc + wa * xa0.x + wb * xa1.x;
        acc[1] = acc[1] * sc + wa * xa0.y + wb * xa1.y;
        acc[2] = acc[2] * sc + wa * xa0.z + wb * xa1.z;
        acc[3] = acc[3] * sc + wa * xa0.w + wb * xa1.w;
        acc[4] = acc[4] * sc + wa * xb0.x + wb * xb1.x;
        acc[5] = acc[5] * sc + wa * xb0.y + wb * xb1.y;
        acc[6] = acc[6] * sc + wa * xb0.z + wb * xb1.z;
        acc[7] = acc[7] * sc + wa * xb0.w + wb * xb1.w;
    }
    if (j < je) {
        int s0 = g_srcs[j]; float w0 = g_ews[j];
        const float4* p0_ = (const float4*)&xl[(long long)s0 * 256 + cb];
        float4 xa0 = p0_[0], xb0 = p0_[1];
        float t0 = edge_logit(xa0, xb0, w0, xrA, xrB, weA, weB, atA, atB);
        float pa = hsum(t0);
        float nm = fmaxf(m, pa);
        float sc = __expf(m - nm);
        float wa = __expf(pa - nm);
        m = nm;
        den = den * sc + wa;
        acc[0] = acc[0] * sc + wa * xa0.x; acc[1] = acc[1] * sc + wa * xa0.y;
        acc[2] = acc[2] * sc + wa * xa0.z; acc[3] = acc[3] * sc + wa * xa0.w;
        acc[4] = acc[4] * sc + wa * xb0.x; acc[5] = acc[5] * sc + wa * xb0.y;
        acc[6] = acc[6] * sc + wa * xb0.z; acc[7] = acc[7] * sc + wa * xb0.w;
    }
    float inv = 1.f / (den + 1e-16f);
    float r8[8];
#pragma unroll
    for (int k = 0; k < 8; k++) {
        float mine = acc[k] * inv;
        float peer = __shfl_xor_sync(0xffffffffu, mine, 16);
        r8[k] = 0.5f * (mine + peer);
    }
    if (lane < 16) {
        float4 bA = *(const float4*)&bias[cb], bB = *(const float4*)&bias[cb + 4];
        float4* po = (float4*)&out[(long long)n * 128 + cb];
        po[0] = make_float4(r8[0] + bA.x, r8[1] + bA.y, r8[2] + bA.z, r8[3] + bA.w);
        po[1] = make_float4(r8[4] + bB.x, r8[5] + bB.y, r8[6] + bB.z, r8[7] + bB.w);
    }
}

// ---------------- launch ----------------
extern "C" void kernel_launch(void* const* d_in, const int* in_sizes, int n_in,
                              void* d_out, int out_size) {
    const float* h       = (const float*)d_in[0];
    const int*   ei      = (const int*)d_in[1];
    const float* ew      = (const float*)d_in[2];
    const float* bn0_g   = (const float*)d_in[3];
    const float* bn0_b   = (const float*)d_in[4];
    const float* bn1_g   = (const float*)d_in[5];
    const float* bn1_b   = (const float*)d_in[6];
    const float* c1_Wl   = (const float*)d_in[7];
    const float* c1_bl   = (const float*)d_in[8];
    const float* c1_Wr   = (const float*)d_in[9];
    const float* c1_br   = (const float*)d_in[10];
    const float* c1_We   = (const float*)d_in[11];
    const float* c1_att  = (const float*)d_in[12];
    const float* c1_bias = (const float*)d_in[13];
    const float* mu_Wl   = (const float*)d_in[14];
    const float* mu_bl   = (const float*)d_in[15];
    const float* mu_Wr   = (const float*)d_in[16];
    const float* mu_br   = (const float*)d_in[17];
    const float* mu_We   = (const float*)d_in[18];
    const float* mu_att  = (const float*)d_in[19];
    const float* mu_bias = (const float*)d_in[20];
    const float* ls_Wl   = (const float*)d_in[21];
    const float* ls_bl   = (const float*)d_in[22];
    const float* ls_Wr   = (const float*)d_in[23];
    const float* ls_br   = (const float*)d_in[24];
    const float* ls_We   = (const float*)d_in[25];
    const float* ls_att  = (const float*)d_in[26];
    const float* ls_bias = (const float*)d_in[27];
    float* out = (float*)d_out;

    const int* src = ei;
    const int* dst = ei + NE;

    float* x4;
    cudaGetSymbolAddress((void**)&x4, g_x4);

    const int TB = 256;
    int eb = (NE + TB - 1) / TB;
    int nodeWarpBlocks = (NN * 32 + TB - 1) / TB;
    int scanBlocks = (NN + 1023) / 1024;   // 49
    const int GEMM_SMEM = 8 * PLN;         // 81920 B

    cudaFuncSetAttribute(k_gemm_mma, cudaFuncAttributeMaxDynamicSharedMemorySize, GEMM_SMEM);

    // fork: side stream runs the CSR chain concurrently with prepw+bn0+lin5
    cudaStream_t s2;
    cudaStreamCreateWithFlags(&s2, cudaStreamNonBlocking);
    cudaEvent_t ef, ej;
    cudaEventCreateWithFlags(&ef, cudaEventDisableTiming);
    cudaEventCreateWithFlags(&ej, cudaEventDisableTiming);

    cudaEventRecord(ef, 0);
    cudaStreamWaitEvent(s2, ef, 0);

    // side stream: CSR build
    k_hist<<<eb, TB, 0, s2>>>(dst);
    k_scan1<<<scanBlocks, 1024, 0, s2>>>();
    k_scan2<<<1, 64, 0, s2>>>(scanBlocks);
    k_scan3<<<scanBlocks, 1024, 0, s2>>>();
    k_scatter<<<eb, TB, 0, s2>>>(src, dst, ew);
    cudaEventRecord(ej, s2);

    // main stream: weight prep + BN0 + conv1 linears
    k_prepw<<<(1024 * 64 + TB - 1) / TB, TB>>>(mu_Wl, mu_Wr, ls_Wl, ls_Wr);
    k_bn0_reduce<<<64, TB>>>(h);
    k_lin5<<<(NN + 31) / 32, TB>>>(h, bn0_g, bn0_b, c1_Wl, c1_bl, c1_Wr, c1_br);

    // join
    cudaStreamWaitEvent(0, ej, 0);

    k_node1<<<nodeWarpBlocks, TB>>>(c1_We, c1_att, c1_bias);

    k_bn1_reduce<<<512, TB>>>();

    k_prepa<<<(NBLK * 128 * 64 + TB - 1) / TB, TB>>>(bn1_g, bn1_b);

    dim3 gg(8, NBLK);
    k_gemm_mma<<<gg, 256, GEMM_SMEM>>>(mu_bl, mu_br, ls_bl, ls_br, x4);

    k_node2h<<<nodeWarpBlocks, TB>>>(x4, x4 + (long long)NN * 256,
                                     mu_We, mu_att, mu_bias, out);
    k_node2h<<<nodeWarpBlocks, TB>>>(x4 + 2ll * NN * 256, x4 + 3ll * NN * 256,
                                     ls_We, ls_att, ls_bias,
                                     out + (long long)NN * 128);
}